// round 11
// baseline (speedup 1.0000x reference)
#include <cuda_runtime.h>

#define KS   13
#define RAD  6
#define TW   16
#define TH   8            // 16x8 outputs per block; 64 threads, 2 vertical outputs each
#define PW   (TW + 2*RAD) // 28
#define PH   (TH + 2*RAD) // 20
#define IMH  256
#define IMW  256
#define NC   4
#define NB   2
#define NT   64

typedef unsigned long long u64;

__device__ __forceinline__ float fast_ex2(float x) {
    float r; asm("ex2.approx.ftz.f32 %0, %1;" : "=f"(r) : "f"(x)); return r;
}
__device__ __forceinline__ u64 addx2(u64 a, u64 b) {
    u64 r; asm("add.rn.f32x2 %0, %1, %2;" : "=l"(r) : "l"(a), "l"(b)); return r;
}
__device__ __forceinline__ u64 fmax2v(u64 a, u64 b, u64 c) {
    u64 r; asm("fma.rn.f32x2 %0, %1, %2, %3;" : "=l"(r) : "l"(a), "l"(b), "l"(c)); return r;
}
__device__ __forceinline__ u64 pack2(float lo, float hi) {
    u64 r; asm("mov.b64 %0, {%1, %2};" : "=l"(r) : "f"(lo), "f"(hi)); return r;
}
__device__ __forceinline__ void unpack2(u64 v, float& lo, float& hi) {
    asm("mov.b64 {%0, %1}, %2;" : "=f"(lo), "=f"(hi) : "l"(v));
}

// 13 taps of one row for one center (f32x2 math), accumulating row partials
#define ROWF(RP, NC01, NC23, PW_, PUV_, PXY_)                                  \
    _Pragma("unroll")                                                          \
    for (int ix = 0; ix < KS; ix++) {                                          \
        const ulonglong2 pv = *reinterpret_cast<const ulonglong2*>(&(RP)[ix]); \
        u64 d01 = addx2(pv.x, NC01);                                           \
        u64 d23 = addx2(pv.y, NC23);                                           \
        float e0, e1, e2, e3;                                                  \
        unpack2(d01, e0, e1);                                                  \
        unpack2(d23, e2, e3);                                                  \
        float m01 = fmaxf(fabsf(e0), fabsf(e1));                               \
        float m23 = fmaxf(fabsf(e2), fabsf(e3));                               \
        float dd  = m01 + m23;                                                 \
        float w   = fast_ex2(__fmaf_rn(dd, -dd, Tx[ix]));                      \
        PW_ += w;                                                              \
        u64 w2 = pack2(w, w);                                                  \
        PUV_ = fmax2v(w2, pv.x, PUV_);                                         \
        PXY_ = fmax2v(w2, pv.y, PXY_);                                         \
    }

__global__ __launch_bounds__(NT)
void bilateral13_v11(const float* __restrict__ x, float* __restrict__ out) {
    __shared__ float4 tile[PH][PW];   // SC * (u01, v01, u23, v23) basis, ~9KB

    const int tid = threadIdx.x;      // 0..63
    const int b   = blockIdx.z;
    const int tx0 = blockIdx.x * TW;
    const int ty0 = blockIdx.y * TH;

    const float K2 = (-0.5f / 9.0f) * 1.4426950408889634f;  // log2 domain
    const float SC = 0.28311592f;                           // sqrt(-K2)

    // ---- cooperative load: reflect pad + pre-scaled (u,v) basis ------------
    const float* xb = x + (size_t)b * NC * IMH * IMW;
    #pragma unroll
    for (int it = 0; it < (PH * PW + NT - 1) / NT; it++) {
        int i = tid + it * NT;
        if (i < PH * PW) {
            int py = i / PW, px = i % PW;
            int gy = ty0 + py - RAD;
            int gx = tx0 + px - RAD;
            gy = (gy < 0) ? -gy : ((gy >= IMH) ? (2 * IMH - 2 - gy) : gy);
            gx = (gx < 0) ? -gx : ((gx >= IMW) ? (2 * IMW - 2 - gx) : gx);
            int g = gy * IMW + gx;
            float p0 = xb[0 * IMH * IMW + g];
            float p1 = xb[1 * IMH * IMW + g];
            float p2 = xb[2 * IMH * IMW + g];
            float p3 = xb[3 * IMH * IMW + g];
            float4 v;
            v.x = SC * (p0 + p1);
            v.y = SC * (p0 - p1);
            v.z = SC * (p2 + p3);
            v.w = SC * (p2 - p3);
            tile[py][px] = v;
        }
    }
    __syncthreads();

    // ---- per-thread: two vertically adjacent outputs -----------------------
    const int lx  = tid & (TW - 1);   // 0..15
    const int lyP = tid >> 4;         // 0..3 -> output rows 2lyP, 2lyP+1
    const int b0  = 2 * lyP;          // first window row (tile coords)

    const float4 c1 = tile[b0 + RAD][lx + RAD];
    const float4 c2 = tile[b0 + RAD + 1][lx + RAD];
    const u64 nc1_01 = pack2(-c1.x, -c1.y);
    const u64 nc1_23 = pack2(-c1.z, -c1.w);
    const u64 nc2_01 = pack2(-c2.x, -c2.y);
    const u64 nc2_23 = pack2(-c2.z, -c2.w);

    // column spatial term, register-resident
    float Tx[KS];
    #pragma unroll
    for (int i = 0; i < KS; i++) {
        float fi = (float)(i - RAD);
        Tx[i] = K2 * fi * fi;
    }

    // totals: scalar wsum + f32x2 vector accumulators
    float s1 = 0.f, s2 = 0.f;
    u64 tUV1 = 0, tXY1 = 0, tUV2 = 0, tXY2 = 0;

    const float gEdge = fast_ex2(K2 * 36.0f);   // ex2(Ty) at |iy-6| = 6

    // ---- j = 0: center1 only (its spatial row 0) ---------------------------
    {
        const float4* rp = &tile[b0][lx];
        float Pw = 0.f; u64 PUV = 0, PXY = 0;
        ROWF(rp, nc1_01, nc1_23, Pw, PUV, PXY)
        u64 gp = pack2(gEdge, gEdge);
        s1   = __fmaf_rn(gEdge, Pw, s1);
        tUV1 = fmax2v(gp, PUV, tUV1);
        tXY1 = fmax2v(gp, PXY, tXY1);
    }

    // ---- j = 1..12: both centers share the row load ------------------------
    #pragma unroll 1
    for (int j = 1; j <= 12; j++) {
        const float4* rp = &tile[b0 + j][lx];
        float P1w = 0.f; u64 P1UV = 0, P1XY = 0;
        float P2w = 0.f; u64 P2UV = 0, P2XY = 0;
        #pragma unroll
        for (int ix = 0; ix < KS; ix++) {
            const ulonglong2 pv = *reinterpret_cast<const ulonglong2*>(&rp[ix]);
            // center 1
            {
                u64 d01 = addx2(pv.x, nc1_01);
                u64 d23 = addx2(pv.y, nc1_23);
                float e0, e1, e2, e3;
                unpack2(d01, e0, e1);
                unpack2(d23, e2, e3);
                float m01 = fmaxf(fabsf(e0), fabsf(e1));
                float m23 = fmaxf(fabsf(e2), fabsf(e3));
                float dd  = m01 + m23;
                float w   = fast_ex2(__fmaf_rn(dd, -dd, Tx[ix]));
                P1w += w;
                u64 w2 = pack2(w, w);
                P1UV = fmax2v(w2, pv.x, P1UV);
                P1XY = fmax2v(w2, pv.y, P1XY);
            }
            // center 2
            {
                u64 d01 = addx2(pv.x, nc2_01);
                u64 d23 = addx2(pv.y, nc2_23);
                float e0, e1, e2, e3;
                unpack2(d01, e0, e1);
                unpack2(d23, e2, e3);
                float m01 = fmaxf(fabsf(e0), fabsf(e1));
                float m23 = fmaxf(fabsf(e2), fabsf(e3));
                float dd  = m01 + m23;
                float w   = fast_ex2(__fmaf_rn(dd, -dd, Tx[ix]));
                P2w += w;
                u64 w2 = pack2(w, w);
                P2UV = fmax2v(w2, pv.x, P2UV);
                P2XY = fmax2v(w2, pv.y, P2XY);
            }
        }
        float a1 = (float)(j - 6);
        float a2 = (float)(j - 7);
        float g1 = fast_ex2(K2 * a1 * a1);
        float g2 = fast_ex2(K2 * a2 * a2);
        u64 g1p = pack2(g1, g1);
        u64 g2p = pack2(g2, g2);
        s1   = __fmaf_rn(g1, P1w, s1);
        tUV1 = fmax2v(g1p, P1UV, tUV1);
        tXY1 = fmax2v(g1p, P1XY, tXY1);
        s2   = __fmaf_rn(g2, P2w, s2);
        tUV2 = fmax2v(g2p, P2UV, tUV2);
        tXY2 = fmax2v(g2p, P2XY, tXY2);
    }

    // ---- j = 13: center2 only (its spatial row 12) -------------------------
    {
        const float4* rp = &tile[b0 + 13][lx];
        float Pw = 0.f; u64 PUV = 0, PXY = 0;
        ROWF(rp, nc2_01, nc2_23, Pw, PUV, PXY)
        u64 gp = pack2(gEdge, gEdge);
        s2   = __fmaf_rn(gEdge, Pw, s2);
        tUV2 = fmax2v(gp, PUV, tUV2);
        tXY2 = fmax2v(gp, PXY, tXY2);
    }

    // ---- epilogue: unpack, undo basis change + pre-scale, normalize --------
    float* ob = out + (size_t)b * NC * IMH * IMW;
    const int y1 = ty0 + 2 * lyP;
    const int o1 = y1 * IMW + tx0 + lx;
    const int o2 = o1 + IMW;

    float U, V, X, Y;
    const float h1 = __fdividef(0.5f, SC * s1);
    unpack2(tUV1, U, V); unpack2(tXY1, X, Y);
    ob[0 * IMH * IMW + o1] = (U + V) * h1;
    ob[1 * IMH * IMW + o1] = (U - V) * h1;
    ob[2 * IMH * IMW + o1] = (X + Y) * h1;
    ob[3 * IMH * IMW + o1] = (X - Y) * h1;

    const float h2 = __fdividef(0.5f, SC * s2);
    unpack2(tUV2, U, V); unpack2(tXY2, X, Y);
    ob[0 * IMH * IMW + o2] = (U + V) * h2;
    ob[1 * IMH * IMW + o2] = (U - V) * h2;
    ob[2 * IMH * IMW + o2] = (X + Y) * h2;
    ob[3 * IMH * IMW + o2] = (X - Y) * h2;
}

extern "C" void kernel_launch(void* const* d_in, const int* in_sizes, int n_in,
                              void* d_out, int out_size) {
    const float* x = (const float*)d_in[0];
    float* out = (float*)d_out;
    dim3 grid(IMW / TW, IMH / TH, NB);   // 16 x 32 x 2 = 1024 blocks
    bilateral13_v11<<<grid, NT>>>(x, out);
}

// round 12
// speedup vs baseline: 1.0152x; 1.0152x over previous
#include <cuda_runtime.h>

#define KS   13
#define RAD  6
#define TW   16
#define TH   8            // 16x8 outputs per block; 64 threads, 2 vertical outputs each
#define PW   (TW + 2*RAD) // 28
#define PH   (TH + 2*RAD) // 20
#define IMH  256
#define IMW  256
#define NC   4
#define NB   2
#define NT   64

typedef unsigned long long u64;

__device__ __forceinline__ float fast_ex2(float x) {
    float r; asm("ex2.approx.ftz.f32 %0, %1;" : "=f"(r) : "f"(x)); return r;
}
__device__ __forceinline__ u64 addx2(u64 a, u64 b) {
    u64 r; asm("add.rn.f32x2 %0, %1, %2;" : "=l"(r) : "l"(a), "l"(b)); return r;
}
__device__ __forceinline__ u64 fmax2v(u64 a, u64 b, u64 c) {
    u64 r; asm("fma.rn.f32x2 %0, %1, %2, %3;" : "=l"(r) : "l"(a), "l"(b), "l"(c)); return r;
}
__device__ __forceinline__ u64 pack2(float lo, float hi) {
    u64 r; asm("mov.b64 %0, {%1, %2};" : "=l"(r) : "f"(lo), "f"(hi)); return r;
}
__device__ __forceinline__ void unpack2(u64 v, float& lo, float& hi) {
    asm("mov.b64 {%0, %1}, %2;" : "=f"(lo), "=f"(hi) : "l"(v));
}

// 13 taps of one row for one center (f32x2 math), accumulating row partials
#define ROWF(RP, NC01, NC23, PW_, PUV_, PXY_)                                  \
    _Pragma("unroll")                                                          \
    for (int ix = 0; ix < KS; ix++) {                                          \
        const ulonglong2 pv = *reinterpret_cast<const ulonglong2*>(&(RP)[ix]); \
        u64 d01 = addx2(pv.x, NC01);                                           \
        u64 d23 = addx2(pv.y, NC23);                                           \
        float e0, e1, e2, e3;                                                  \
        unpack2(d01, e0, e1);                                                  \
        unpack2(d23, e2, e3);                                                  \
        float m01 = fmaxf(fabsf(e0), fabsf(e1));                               \
        float m23 = fmaxf(fabsf(e2), fabsf(e3));                               \
        float dd  = m01 + m23;                                                 \
        float w   = fast_ex2(__fmaf_rn(dd, -dd, Tx[ix]));                      \
        PW_ += w;                                                              \
        u64 w2 = pack2(w, w);                                                  \
        PUV_ = fmax2v(w2, pv.x, PUV_);                                         \
        PXY_ = fmax2v(w2, pv.y, PXY_);                                         \
    }

__global__ __launch_bounds__(NT)
void bilateral13_v12(const float* __restrict__ x, float* __restrict__ out) {
    __shared__ float4 tile[PH][PW];   // SC * (u01, v01, u23, v23) basis, ~9KB

    const int tid = threadIdx.x;      // 0..63
    const int b   = blockIdx.z;
    const int tx0 = blockIdx.x * TW;
    const int ty0 = blockIdx.y * TH;

    const float K2 = (-0.5f / 9.0f) * 1.4426950408889634f;  // log2 domain
    const float SC = 0.28311592f;                           // sqrt(-K2)

    // ---- cooperative load: reflect pad + pre-scaled (u,v) basis ------------
    const float* xb = x + (size_t)b * NC * IMH * IMW;
    #pragma unroll
    for (int it = 0; it < (PH * PW + NT - 1) / NT; it++) {
        int i = tid + it * NT;
        if (i < PH * PW) {
            int py = i / PW, px = i % PW;
            int gy = ty0 + py - RAD;
            int gx = tx0 + px - RAD;
            gy = (gy < 0) ? -gy : ((gy >= IMH) ? (2 * IMH - 2 - gy) : gy);
            gx = (gx < 0) ? -gx : ((gx >= IMW) ? (2 * IMW - 2 - gx) : gx);
            int g = gy * IMW + gx;
            float p0 = xb[0 * IMH * IMW + g];
            float p1 = xb[1 * IMH * IMW + g];
            float p2 = xb[2 * IMH * IMW + g];
            float p3 = xb[3 * IMH * IMW + g];
            float4 v;
            v.x = SC * (p0 + p1);
            v.y = SC * (p0 - p1);
            v.z = SC * (p2 + p3);
            v.w = SC * (p2 - p3);
            tile[py][px] = v;
        }
    }
    __syncthreads();

    // ---- per-thread: two vertically adjacent outputs -----------------------
    const int lx  = tid & (TW - 1);   // 0..15
    const int lyP = tid >> 4;         // 0..3 -> output rows 2lyP, 2lyP+1
    const int b0  = 2 * lyP;          // first window row (tile coords)

    const float4 c1 = tile[b0 + RAD][lx + RAD];
    const float4 c2 = tile[b0 + RAD + 1][lx + RAD];
    const u64 nc1_01 = pack2(-c1.x, -c1.y);
    const u64 nc1_23 = pack2(-c1.z, -c1.w);
    const u64 nc2_01 = pack2(-c2.x, -c2.y);
    const u64 nc2_23 = pack2(-c2.z, -c2.w);

    // column spatial term, register-resident
    float Tx[KS];
    #pragma unroll
    for (int i = 0; i < KS; i++) {
        float fi = (float)(i - RAD);
        Tx[i] = K2 * fi * fi;
    }

    // totals: scalar wsum + f32x2 vector accumulators
    float s1 = 0.f, s2 = 0.f;
    u64 tUV1 = 0, tXY1 = 0, tUV2 = 0, tXY2 = 0;

    const float gEdge = fast_ex2(K2 * 36.0f);   // ex2(Ty) at |iy-6| = 6

    // ---- j = 0: center1 only (its spatial row 0) ---------------------------
    {
        const float4* rp = &tile[b0][lx];
        float Pw = 0.f; u64 PUV = 0, PXY = 0;
        ROWF(rp, nc1_01, nc1_23, Pw, PUV, PXY)
        u64 gp = pack2(gEdge, gEdge);
        s1   = __fmaf_rn(gEdge, Pw, s1);
        tUV1 = fmax2v(gp, PUV, tUV1);
        tXY1 = fmax2v(gp, PXY, tXY1);
    }

    // ---- j = 1..12: both centers share the row load; 2 rows in flight ------
    #pragma unroll 2
    for (int j = 1; j <= 12; j++) {
        const float4* rp = &tile[b0 + j][lx];
        float P1w = 0.f; u64 P1UV = 0, P1XY = 0;
        float P2w = 0.f; u64 P2UV = 0, P2XY = 0;
        #pragma unroll
        for (int ix = 0; ix < KS; ix++) {
            const ulonglong2 pv = *reinterpret_cast<const ulonglong2*>(&rp[ix]);
            // center 1
            {
                u64 d01 = addx2(pv.x, nc1_01);
                u64 d23 = addx2(pv.y, nc1_23);
                float e0, e1, e2, e3;
                unpack2(d01, e0, e1);
                unpack2(d23, e2, e3);
                float m01 = fmaxf(fabsf(e0), fabsf(e1));
                float m23 = fmaxf(fabsf(e2), fabsf(e3));
                float dd  = m01 + m23;
                float w   = fast_ex2(__fmaf_rn(dd, -dd, Tx[ix]));
                P1w += w;
                u64 w2 = pack2(w, w);
                P1UV = fmax2v(w2, pv.x, P1UV);
                P1XY = fmax2v(w2, pv.y, P1XY);
            }
            // center 2
            {
                u64 d01 = addx2(pv.x, nc2_01);
                u64 d23 = addx2(pv.y, nc2_23);
                float e0, e1, e2, e3;
                unpack2(d01, e0, e1);
                unpack2(d23, e2, e3);
                float m01 = fmaxf(fabsf(e0), fabsf(e1));
                float m23 = fmaxf(fabsf(e2), fabsf(e3));
                float dd  = m01 + m23;
                float w   = fast_ex2(__fmaf_rn(dd, -dd, Tx[ix]));
                P2w += w;
                u64 w2 = pack2(w, w);
                P2UV = fmax2v(w2, pv.x, P2UV);
                P2XY = fmax2v(w2, pv.y, P2XY);
            }
        }
        float a1 = (float)(j - 6);
        float a2 = (float)(j - 7);
        float g1 = fast_ex2(K2 * a1 * a1);
        float g2 = fast_ex2(K2 * a2 * a2);
        u64 g1p = pack2(g1, g1);
        u64 g2p = pack2(g2, g2);
        s1   = __fmaf_rn(g1, P1w, s1);
        tUV1 = fmax2v(g1p, P1UV, tUV1);
        tXY1 = fmax2v(g1p, P1XY, tXY1);
        s2   = __fmaf_rn(g2, P2w, s2);
        tUV2 = fmax2v(g2p, P2UV, tUV2);
        tXY2 = fmax2v(g2p, P2XY, tXY2);
    }

    // ---- j = 13: center2 only (its spatial row 12) -------------------------
    {
        const float4* rp = &tile[b0 + 13][lx];
        float Pw = 0.f; u64 PUV = 0, PXY = 0;
        ROWF(rp, nc2_01, nc2_23, Pw, PUV, PXY)
        u64 gp = pack2(gEdge, gEdge);
        s2   = __fmaf_rn(gEdge, Pw, s2);
        tUV2 = fmax2v(gp, PUV, tUV2);
        tXY2 = fmax2v(gp, PXY, tXY2);
    }

    // ---- epilogue: unpack, undo basis change + pre-scale, normalize --------
    float* ob = out + (size_t)b * NC * IMH * IMW;
    const int y1 = ty0 + 2 * lyP;
    const int o1 = y1 * IMW + tx0 + lx;
    const int o2 = o1 + IMW;

    float U, V, X, Y;
    const float h1 = __fdividef(0.5f, SC * s1);
    unpack2(tUV1, U, V); unpack2(tXY1, X, Y);
    ob[0 * IMH * IMW + o1] = (U + V) * h1;
    ob[1 * IMH * IMW + o1] = (U - V) * h1;
    ob[2 * IMH * IMW + o1] = (X + Y) * h1;
    ob[3 * IMH * IMW + o1] = (X - Y) * h1;

    const float h2 = __fdividef(0.5f, SC * s2);
    unpack2(tUV2, U, V); unpack2(tXY2, X, Y);
    ob[0 * IMH * IMW + o2] = (U + V) * h2;
    ob[1 * IMH * IMW + o2] = (U - V) * h2;
    ob[2 * IMH * IMW + o2] = (X + Y) * h2;
    ob[3 * IMH * IMW + o2] = (X - Y) * h2;
}

extern "C" void kernel_launch(void* const* d_in, const int* in_sizes, int n_in,
                              void* d_out, int out_size) {
    const float* x = (const float*)d_in[0];
    float* out = (float*)d_out;
    dim3 grid(IMW / TW, IMH / TH, NB);   // 16 x 32 x 2 = 1024 blocks
    bilateral13_v12<<<grid, NT>>>(x, out);
}